// round 7
// baseline (speedup 1.0000x reference)
#include <cuda_runtime.h>
#include <cuda_bf16.h>
#include <stdint.h>

// Hopfield layer via warp-level bf16 mma.sync (sm_100 target, no tcgen05).
// R7: 8 warps x 32 query rows per warp (QT=256) -> halves per-row smem crossbar
// traffic vs R6 while keeping 2 warps/SMSP. Pre-split bf16 hi/lo inputs,
// cp.async double-buffered KV tiles, 3-term error-corrected bf16 GEMMs,
// fp32 accum, unnormalized softmax (bounded scores), normalize at end.

#define DM 512
#define QT 256     // query rows per CTA (8 warps x 32 rows)
#define ST 64      // kv rows per tile
#define THREADS 256

// dynamic smem layout (bytes)
#define KH0 0
#define KH1 8192
#define KL0 16384
#define KL1 24576
#define QH0 32768
#define QL0 65536
#define SMEM_TOTAL 98304

#define NELEM (2u * 2048u * 512u)
__device__ __nv_bfloat16 gYh[NELEM], gYl[NELEM];
__device__ __nv_bfloat16 gRh[NELEM], gRl[NELEM];
__device__ __nv_bfloat16 gTh[NELEM], gTl[NELEM];

static __device__ __forceinline__ uint32_t s2u(const void* p) {
    uint32_t a;
    asm("{ .reg .u64 t; cvta.to.shared.u64 t, %1; cvt.u32.u64 %0, t; }"
        : "=r"(a) : "l"(p));
    return a;
}
// swizzled byte offset of (row, 16B-chunk) in a 128B-row tile
static __device__ __forceinline__ uint32_t off(int row, int chunk) {
    return (uint32_t)(row * 128 + ((chunk ^ (row & 7)) << 4));
}
static __device__ __forceinline__ float ex2f_(float x) {
    float r; asm("ex2.approx.ftz.f32 %0, %1;" : "=f"(r) : "f"(x)); return r;
}
static __device__ __forceinline__ void splitpack(float x, float y,
                                                 uint32_t& hi, uint32_t& lo) {
    __nv_bfloat16 hx = __float2bfloat16_rn(x), hy = __float2bfloat16_rn(y);
    float rx = x - __bfloat162float(hx), ry = y - __bfloat162float(hy);
    __nv_bfloat16 lx = __float2bfloat16_rn(rx), ly = __float2bfloat16_rn(ry);
    hi = ((uint32_t)__bfloat16_as_ushort(hy) << 16) | (uint32_t)__bfloat16_as_ushort(hx);
    lo = ((uint32_t)__bfloat16_as_ushort(ly) << 16) | (uint32_t)__bfloat16_as_ushort(lx);
}

static __device__ __forceinline__ void mma_bf16(float c[4], const uint32_t a[4],
                                                const uint32_t b[2]) {
    asm volatile(
        "mma.sync.aligned.m16n8k16.row.col.f32.bf16.bf16.f32 "
        "{%0,%1,%2,%3}, {%4,%5,%6,%7}, {%8,%9}, {%0,%1,%2,%3};"
        : "+f"(c[0]), "+f"(c[1]), "+f"(c[2]), "+f"(c[3])
        : "r"(a[0]), "r"(a[1]), "r"(a[2]), "r"(a[3]), "r"(b[0]), "r"(b[1]));
}
#define LDSM4(r, a) \
    asm volatile("ldmatrix.sync.aligned.m8n8.x4.shared.b16 {%0,%1,%2,%3}, [%4];" \
        : "=r"((r)[0]), "=r"((r)[1]), "=r"((r)[2]), "=r"((r)[3]) : "r"(a))
#define LDSM4T(r, a) \
    asm volatile("ldmatrix.sync.aligned.m8n8.x4.trans.shared.b16 {%0,%1,%2,%3}, [%4];" \
        : "=r"((r)[0]), "=r"((r)[1]), "=r"((r)[2]), "=r"((r)[3]) : "r"(a))
#define CPA(dst, src) \
    asm volatile("cp.async.cg.shared.global [%0], [%1], 16;" :: "r"(dst), "l"(src))
#define CPC() asm volatile("cp.async.commit_group;" ::: "memory")
#define CPW(n) asm volatile("cp.async.wait_group %0;" :: "n"(n) : "memory")

__global__ void presplit(const float4* __restrict__ src, uint2* __restrict__ hi,
                         uint2* __restrict__ lo, int n4)
{
    int i = blockIdx.x * blockDim.x + threadIdx.x;
    if (i < n4) {
        float4 x = src[i];
        uint32_t h0, l0, h1, l1;
        splitpack(x.x, x.y, h0, l0);
        splitpack(x.z, x.w, h1, l1);
        hi[i] = make_uint2(h0, h1);
        lo[i] = make_uint2(l0, l1);
    }
}

__global__ __launch_bounds__(THREADS, 1)
void hopfield_mma(const __nv_bfloat16* __restrict__ Qh, const __nv_bfloat16* __restrict__ Ql,
                  const __nv_bfloat16* __restrict__ Kh, const __nv_bfloat16* __restrict__ Kl,
                  float* __restrict__ outF,
                  __nv_bfloat16* __restrict__ outH, __nv_bfloat16* __restrict__ outL,
                  int L, int S)
{
    extern __shared__ __align__(16) uint8_t smem[];
    const uint32_t sb = s2u(smem);
    const uint32_t khB[2] = { sb + KH0, sb + KH1 };
    const uint32_t klB[2] = { sb + KL0, sb + KL1 };
    const uint32_t qhB = sb + QH0, qlB = sb + QL0;

    const int tid = threadIdx.x;
    const int wid = tid >> 5;
    const int lane = tid & 31;
    const int h = blockIdx.y, b = blockIdx.z;
    const float C = 0.125f * 1.4426950408889634f;

    // ---- stage full Q tile (256 rows, hi+lo) ----
    const __nv_bfloat16* qg = Qh + ((size_t)b * L + (size_t)blockIdx.x * QT) * DM + h * 64;
    const __nv_bfloat16* qgl = Ql + ((size_t)b * L + (size_t)blockIdx.x * QT) * DM + h * 64;
    {
        int c = tid & 7, r0 = tid >> 3;   // 0..31
#pragma unroll
        for (int i = 0; i < 8; i++) {
            int row = r0 + i * 32;        // 0..255
            CPA(qhB + off(row, c), (const char*)(qg + (size_t)row * DM) + c * 16);
            CPA(qlB + off(row, c), (const char*)(qgl + (size_t)row * DM) + c * 16);
        }
        CPC(); CPW(0);
    }
    __syncthreads();

    // per-warp A fragments: 2 row-tiles of 16x64 (hi/lo); warp w owns rows 32w..32w+31
    uint32_t qfh[2][4][4], qfl[2][4][4];
#pragma unroll
    for (int rt = 0; rt < 2; rt++) {
        int gr = 32 * wid + 16 * rt + (lane & 15);
#pragma unroll
        for (int t = 0; t < 4; t++) {
            int ch = 2 * t + (lane >> 4);
            LDSM4(qfh[rt][t], qhB + off(gr, ch));
            LDSM4(qfl[rt][t], qlB + off(gr, ch));
        }
    }

    float oacc[2][8][4];
#pragma unroll
    for (int rt = 0; rt < 2; rt++)
#pragma unroll
        for (int j = 0; j < 8; j++)
#pragma unroll
            for (int i = 0; i < 4; i++) oacc[rt][j][i] = 0.f;
    float lsum[2][2] = {{0.f, 0.f}, {0.f, 0.f}};

    const __nv_bfloat16* kg = Kh + (size_t)b * S * DM + h * 64;
    const __nv_bfloat16* kgl = Kl + (size_t)b * S * DM + h * 64;
    const int NT = S / ST;   // 32

    // prefetch tiles 0, 1
    {
        int c = tid & 7, r0 = tid >> 3;
#pragma unroll
        for (int pf = 0; pf < 2; pf++) {
            const char* hs = (const char*)(kg + (size_t)pf * ST * DM);
            const char* ls = (const char*)(kgl + (size_t)pf * ST * DM);
#pragma unroll
            for (int i = 0; i < 2; i++) {
                int row = r0 + i * 32;
                CPA(khB[pf] + off(row, c), hs + (size_t)row * DM * 2 + c * 16);
                CPA(klB[pf] + off(row, c), ls + (size_t)row * DM * 2 + c * 16);
            }
            CPC();
        }
    }

    for (int t = 0; t < NT; t++) {
        CPW(1);
        __syncthreads();
        const uint32_t hbb = khB[t & 1];
        const uint32_t lbb = klB[t & 1];

        // ---- GEMM1: sc[rt][16 x 64] = Q x K^T (3 split terms) ----
        float sc[2][8][4];
#pragma unroll
        for (int rt = 0; rt < 2; rt++)
#pragma unroll
            for (int j = 0; j < 8; j++)
#pragma unroll
                for (int i = 0; i < 4; i++) sc[rt][j][i] = 0.f;

#pragma unroll
        for (int j = 0; j < 8; j++) {
            int row = 8 * j + (lane & 7);
            uint32_t bh[8], bl[8];
            LDSM4(bh + 0, hbb + off(row, (lane >> 3)));
            LDSM4(bh + 4, hbb + off(row, 4 + (lane >> 3)));
            LDSM4(bl + 0, lbb + off(row, (lane >> 3)));
            LDSM4(bl + 4, lbb + off(row, 4 + (lane >> 3)));
#pragma unroll
            for (int t4 = 0; t4 < 4; t4++) {
#pragma unroll
                for (int rt = 0; rt < 2; rt++) {
                    mma_bf16(sc[rt][j], qfh[rt][t4], bh + 2 * t4);
                    mma_bf16(sc[rt][j], qfh[rt][t4], bl + 2 * t4);
                    mma_bf16(sc[rt][j], qfl[rt][t4], bh + 2 * t4);
                }
            }
        }

        // ---- softmax (unnormalized), pack P to A-fragments ----
        uint32_t ph[2][4][4], pl[2][4][4];
#pragma unroll
        for (int rt = 0; rt < 2; rt++) {
#pragma unroll
            for (int t4 = 0; t4 < 4; t4++) {
                float e0 = ex2f_(sc[rt][2 * t4][0] * C),     e1 = ex2f_(sc[rt][2 * t4][1] * C);
                float e2 = ex2f_(sc[rt][2 * t4][2] * C),     e3 = ex2f_(sc[rt][2 * t4][3] * C);
                float e4 = ex2f_(sc[rt][2 * t4 + 1][0] * C), e5 = ex2f_(sc[rt][2 * t4 + 1][1] * C);
                float e6 = ex2f_(sc[rt][2 * t4 + 1][2] * C), e7 = ex2f_(sc[rt][2 * t4 + 1][3] * C);
                lsum[rt][0] += (e0 + e1) + (e4 + e5);
                lsum[rt][1] += (e2 + e3) + (e6 + e7);
                splitpack(e0, e1, ph[rt][t4][0], pl[rt][t4][0]);
                splitpack(e2, e3, ph[rt][t4][1], pl[rt][t4][1]);
                splitpack(e4, e5, ph[rt][t4][2], pl[rt][t4][2]);
                splitpack(e6, e7, ph[rt][t4][3], pl[rt][t4][3]);
            }
        }

        // ---- GEMM2: O += P x V (V == K tile, .trans; V frags shared over rt) ----
#pragma unroll
        for (int t4 = 0; t4 < 4; t4++) {
            int row = 16 * t4 + (lane & 7) + (lane & 8);
#pragma unroll
            for (int jp = 0; jp < 4; jp++) {
                int ch = 2 * jp + (lane >> 4);
                uint32_t vh[4], vl[4];
                LDSM4T(vh, hbb + off(row, ch));
                LDSM4T(vl, lbb + off(row, ch));
#pragma unroll
                for (int rt = 0; rt < 2; rt++) {
                    mma_bf16(oacc[rt][2 * jp],     ph[rt][t4], vh + 0);
                    mma_bf16(oacc[rt][2 * jp],     ph[rt][t4], vl + 0);
                    mma_bf16(oacc[rt][2 * jp],     pl[rt][t4], vh + 0);
                    mma_bf16(oacc[rt][2 * jp + 1], ph[rt][t4], vh + 2);
                    mma_bf16(oacc[rt][2 * jp + 1], ph[rt][t4], vl + 2);
                    mma_bf16(oacc[rt][2 * jp + 1], pl[rt][t4], vh + 2);
                }
            }
        }
        __syncthreads();

        // prefetch tile t+2 into the buffer just freed
        if (t + 2 < NT) {
            int c = tid & 7, r0 = tid >> 3;
            const char* hs = (const char*)(kg + (size_t)(t + 2) * ST * DM);
            const char* ls = (const char*)(kgl + (size_t)(t + 2) * ST * DM);
#pragma unroll
            for (int i = 0; i < 2; i++) {
                int row = r0 + i * 32;
                CPA(hbb + off(row, c), hs + (size_t)row * DM * 2 + c * 16);
                CPA(lbb + off(row, c), ls + (size_t)row * DM * 2 + c * 16);
            }
        }
        CPC();
    }

    // ---- normalize + store ----
    const int r = lane >> 2, cb = (lane & 3) * 2;
#pragma unroll
    for (int rt = 0; rt < 2; rt++) {
        float l0 = lsum[rt][0], l1 = lsum[rt][1];
        l0 += __shfl_xor_sync(0xffffffffu, l0, 1);
        l0 += __shfl_xor_sync(0xffffffffu, l0, 2);
        l1 += __shfl_xor_sync(0xffffffffu, l1, 1);
        l1 += __shfl_xor_sync(0xffffffffu, l1, 2);
        float inv0 = 1.f / l0, inv1 = 1.f / l1;

        size_t base = ((size_t)b * L + (size_t)blockIdx.x * QT + 32 * wid + 16 * rt) * DM
                    + h * 64;
        if (outF) {
#pragma unroll
            for (int j = 0; j < 8; j++) {
                *(float2*)(outF + base + (size_t)r * DM + 8 * j + cb) =
                    make_float2(oacc[rt][j][0] * inv0, oacc[rt][j][1] * inv0);
                *(float2*)(outF + base + (size_t)(r + 8) * DM + 8 * j + cb) =
                    make_float2(oacc[rt][j][2] * inv1, oacc[rt][j][3] * inv1);
            }
        } else {
#pragma unroll
            for (int j = 0; j < 8; j++) {
                uint32_t h0, lp0, h1, lp1;
                splitpack(oacc[rt][j][0] * inv0, oacc[rt][j][1] * inv0, h0, lp0);
                splitpack(oacc[rt][j][2] * inv1, oacc[rt][j][3] * inv1, h1, lp1);
                *(uint32_t*)(outH + base + (size_t)r * DM + 8 * j + cb) = h0;
                *(uint32_t*)(outL + base + (size_t)r * DM + 8 * j + cb) = lp0;
                *(uint32_t*)(outH + base + (size_t)(r + 8) * DM + 8 * j + cb) = h1;
                *(uint32_t*)(outL + base + (size_t)(r + 8) * DM + 8 * j + cb) = lp1;
            }
        }
    }
}

extern "C" void kernel_launch(void* const* d_in, const int* in_sizes, int n_in,
                              void* d_out, int out_size)
{
    const float* R = (const float*)d_in[0];
    const float* Y = (const float*)d_in[1];
    float* out = (float*)d_out;

    const int B = 2, H = 8;
    const int L = in_sizes[0] / (B * DM);   // 2048
    const int S = in_sizes[1] / (B * DM);   // 2048

    __nv_bfloat16 *Yh, *Yl, *Rh, *Rl, *Th, *Tl;
    cudaGetSymbolAddress((void**)&Yh, gYh);
    cudaGetSymbolAddress((void**)&Yl, gYl);
    cudaGetSymbolAddress((void**)&Rh, gRh);
    cudaGetSymbolAddress((void**)&Rl, gRl);
    cudaGetSymbolAddress((void**)&Th, gTh);
    cudaGetSymbolAddress((void**)&Tl, gTl);

    cudaFuncSetAttribute(hopfield_mma, cudaFuncAttributeMaxDynamicSharedMemorySize,
                         SMEM_TOTAL);

    const int n4 = (int)(NELEM / 4);
    presplit<<<(n4 + 255) / 256, 256>>>((const float4*)Y, (uint2*)Yh, (uint2*)Yl, n4);
    presplit<<<(n4 + 255) / 256, 256>>>((const float4*)R, (uint2*)Rh, (uint2*)Rl, n4);

    dim3 grid(L / QT, H, B);
    dim3 block(THREADS);
    // step 1: Q=R -> split tmp
    hopfield_mma<<<grid, block, SMEM_TOTAL>>>(Rh, Rl, Yh, Yl, nullptr, Th, Tl, L, S);
    // step 2: Q=tmp -> fp32 out
    hopfield_mma<<<grid, block, SMEM_TOTAL>>>(Th, Tl, Yh, Yl, out, nullptr, nullptr, L, S);
}

// round 8
// speedup vs baseline: 1.0850x; 1.0850x over previous
#include <cuda_runtime.h>
#include <cuda_bf16.h>
#include <stdint.h>

// Hopfield layer via warp-level bf16 mma.sync (sm_100 target, no tcgen05).
// R8: R6 config (8 warps x 16 query rows) but split into TWO independent
// 4-warp groups, each with its own triple-buffered KV smem and named barrier.
// One warp per group per SMSP -> cross-group co-issue hides LDSM/barrier
// latency. Prefetch issued 2 tiles ahead. 3-term error-corrected bf16 GEMMs,
// fp32 accum, unnormalized softmax (bounded scores), normalize at end.

#define DM 512
#define QT 128     // query rows per CTA (8 warps x 16 rows)
#define ST 64      // kv rows per tile
#define THREADS 256

#define BUF_STRIDE 16384            // hi(8K) + lo(8K) per buffer
#define GRP_STRIDE (3 * BUF_STRIDE) // 3 buffers per group
#define SMEM_TOTAL (2 * GRP_STRIDE) // 98304

#define NELEM (2u * 2048u * 512u)
__device__ __nv_bfloat16 gYh[NELEM], gYl[NELEM];
__device__ __nv_bfloat16 gRh[NELEM], gRl[NELEM];
__device__ __nv_bfloat16 gTh[NELEM], gTl[NELEM];

static __device__ __forceinline__ uint32_t s2u(const void* p) {
    uint32_t a;
    asm("{ .reg .u64 t; cvta.to.shared.u64 t, %1; cvt.u32.u64 %0, t; }"
        : "=r"(a) : "l"(p));
    return a;
}
static __device__ __forceinline__ uint32_t off(int row, int chunk) {
    return (uint32_t)(row * 128 + ((chunk ^ (row & 7)) << 4));
}
static __device__ __forceinline__ float ex2f_(float x) {
    float r; asm("ex2.approx.ftz.f32 %0, %1;" : "=f"(r) : "f"(x)); return r;
}
static __device__ __forceinline__ void splitpack(float x, float y,
                                                 uint32_t& hi, uint32_t& lo) {
    __nv_bfloat16 hx = __float2bfloat16_rn(x), hy = __float2bfloat16_rn(y);
    float rx = x - __bfloat162float(hx), ry = y - __bfloat162float(hy);
    __nv_bfloat16 lx = __float2bfloat16_rn(rx), ly = __float2bfloat16_rn(ry);
    hi = ((uint32_t)__bfloat16_as_ushort(hy) << 16) | (uint32_t)__bfloat16_as_ushort(hx);
    lo = ((uint32_t)__bfloat16_as_ushort(ly) << 16) | (uint32_t)__bfloat16_as_ushort(lx);
}

static __device__ __forceinline__ void mma_bf16(float c[4], const uint32_t a[4],
                                                const uint32_t b[2]) {
    asm volatile(
        "mma.sync.aligned.m16n8k16.row.col.f32.bf16.bf16.f32 "
        "{%0,%1,%2,%3}, {%4,%5,%6,%7}, {%8,%9}, {%0,%1,%2,%3};"
        : "+f"(c[0]), "+f"(c[1]), "+f"(c[2]), "+f"(c[3])
        : "r"(a[0]), "r"(a[1]), "r"(a[2]), "r"(a[3]), "r"(b[0]), "r"(b[1]));
}
#define LDSM4(r, a) \
    asm volatile("ldmatrix.sync.aligned.m8n8.x4.shared.b16 {%0,%1,%2,%3}, [%4];" \
        : "=r"((r)[0]), "=r"((r)[1]), "=r"((r)[2]), "=r"((r)[3]) : "r"(a))
#define LDSM4T(r, a) \
    asm volatile("ldmatrix.sync.aligned.m8n8.x4.trans.shared.b16 {%0,%1,%2,%3}, [%4];" \
        : "=r"((r)[0]), "=r"((r)[1]), "=r"((r)[2]), "=r"((r)[3]) : "r"(a))
#define CPA(dst, src) \
    asm volatile("cp.async.cg.shared.global [%0], [%1], 16;" :: "r"(dst), "l"(src))
#define CPC() asm volatile("cp.async.commit_group;" ::: "memory")
#define CPW(n) asm volatile("cp.async.wait_group %0;" :: "n"(n) : "memory")
#define BARG(id) asm volatile("bar.sync %0, 128;" :: "r"(id) : "memory")

__global__ void presplit(const float4* __restrict__ src, uint2* __restrict__ hi,
                         uint2* __restrict__ lo, int n4)
{
    int i = blockIdx.x * blockDim.x + threadIdx.x;
    if (i < n4) {
        float4 x = src[i];
        uint32_t h0, l0, h1, l1;
        splitpack(x.x, x.y, h0, l0);
        splitpack(x.z, x.w, h1, l1);
        hi[i] = make_uint2(h0, h1);
        lo[i] = make_uint2(l0, l1);
    }
}

// fetch one 64-row tile plane (hi+lo) into a buffer; 128 group threads
static __device__ __forceinline__ void fetch_tile(uint32_t bh, uint32_t bl,
                                                  const __nv_bfloat16* hsrc,
                                                  const __nv_bfloat16* lsrc,
                                                  int gtid) {
    int c = gtid & 7, r0 = gtid >> 3;   // 0..15
#pragma unroll
    for (int i = 0; i < 4; i++) {
        int row = r0 + 16 * i;
        CPA(bh + off(row, c), (const char*)(hsrc + (size_t)row * DM) + c * 16);
        CPA(bl + off(row, c), (const char*)(lsrc + (size_t)row * DM) + c * 16);
    }
}

__global__ __launch_bounds__(THREADS, 1)
void hopfield_mma(const __nv_bfloat16* __restrict__ Qh, const __nv_bfloat16* __restrict__ Ql,
                  const __nv_bfloat16* __restrict__ Kh, const __nv_bfloat16* __restrict__ Kl,
                  float* __restrict__ outF,
                  __nv_bfloat16* __restrict__ outH, __nv_bfloat16* __restrict__ outL,
                  int L, int S)
{
    extern __shared__ __align__(16) uint8_t smem[];
    const int tid = threadIdx.x;
    const int wid = tid >> 5;
    const int lane = tid & 31;
    const int g = wid >> 2;          // group 0 or 1
    const int gtid = tid & 127;
    const int barid = 1 + g;
    const int h = blockIdx.y, b = blockIdx.z;
    const float C = 0.125f * 1.4426950408889634f;

    const uint32_t gb = s2u(smem) + (uint32_t)g * GRP_STRIDE;
    uint32_t bufH[3], bufL[3];
#pragma unroll
    for (int i = 0; i < 3; i++) {
        bufH[i] = gb + i * BUF_STRIDE;
        bufL[i] = bufH[i] + 8192;
    }

    // ---- stage this group's 64 Q rows through buffer 0 ----
    size_t qrow0 = (size_t)b * L + (size_t)blockIdx.x * QT + 64 * g;
    fetch_tile(bufH[0], bufL[0], Qh + qrow0 * DM + h * 64, Ql + qrow0 * DM + h * 64, gtid);
    CPC(); CPW(0);
    BARG(barid);

    // per-warp A fragments: 16x64 (hi/lo); warp (wid&3) owns local rows 16w..16w+15
    uint32_t qfh[4][4], qfl[4][4];
    {
        int lr = 16 * (wid & 3) + (lane & 15);
#pragma unroll
        for (int t = 0; t < 4; t++) {
            int ch = 2 * t + (lane >> 4);
            LDSM4(qfh[t], bufH[0] + off(lr, ch));
            LDSM4(qfl[t], bufL[0] + off(lr, ch));
        }
    }
    BARG(barid);   // frag reads done before KV overwrites buffer 0

    float oacc[8][4];
#pragma unroll
    for (int j = 0; j < 8; j++)
#pragma unroll
        for (int i = 0; i < 4; i++) oacc[j][i] = 0.f;
    float l0 = 0.f, l1 = 0.f;

    const __nv_bfloat16* kg = Kh + (size_t)b * S * DM + h * 64;
    const __nv_bfloat16* kgl = Kl + (size_t)b * S * DM + h * 64;
    const int NT = S / ST;   // 32

    // prefetch tiles 0, 1
    fetch_tile(bufH[0], bufL[0], kg, kgl, gtid);
    CPC();
    fetch_tile(bufH[1], bufL[1], kg + (size_t)ST * DM, kgl + (size_t)ST * DM, gtid);
    CPC();

    for (int t = 0; t < NT; t++) {
        // prefetch t+2 into the buffer freed at end of iter t-1
        if (t + 2 < NT) {
            int bi = (t + 2) % 3;
            fetch_tile(bufH[bi], bufL[bi],
                       kg + (size_t)(t + 2) * ST * DM, kgl + (size_t)(t + 2) * ST * DM, gtid);
        }
        CPC();
        CPW(2);          // tile t complete (t+1, t+2 may be in flight)
        BARG(barid);

        const uint32_t hbb = bufH[t % 3];
        const uint32_t lbb = bufL[t % 3];

        // ---- GEMM1: sc[16 x 64] = Q x K^T (3 split terms) ----
        float sc[8][4];
#pragma unroll
        for (int j = 0; j < 8; j++)
#pragma unroll
            for (int i = 0; i < 4; i++) sc[j][i] = 0.f;

#pragma unroll
        for (int j = 0; j < 8; j++) {
            int row = 8 * j + (lane & 7);
            uint32_t bh[8], bl[8];
            LDSM4(bh + 0, hbb + off(row, (lane >> 3)));
            LDSM4(bh + 4, hbb + off(row, 4 + (lane >> 3)));
            LDSM4(bl + 0, lbb + off(row, (lane >> 3)));
            LDSM4(bl + 4, lbb + off(row, 4 + (lane >> 3)));
#pragma unroll
            for (int t4 = 0; t4 < 4; t4++) {
                mma_bf16(sc[j], qfh[t4], bh + 2 * t4);
                mma_bf16(sc[j], qfh[t4], bl + 2 * t4);
                mma_bf16(sc[j], qfl[t4], bh + 2 * t4);
            }
        }

        // ---- softmax (unnormalized), pack P to A-fragments ----
        uint32_t ph[4][4], pl[4][4];
#pragma unroll
        for (int t4 = 0; t4 < 4; t4++) {
            float e0 = ex2f_(sc[2 * t4][0] * C),     e1 = ex2f_(sc[2 * t4][1] * C);
            float e2 = ex2f_(sc[2 * t4][2] * C),     e3 = ex2f_(sc[2 * t4][3] * C);
            float e4 = ex2f_(sc[2 * t4 + 1][0] * C), e5 = ex2f_(sc[2 * t4 + 1][1] * C);
            float e6 = ex2f_(sc[2 * t4 + 1][2] * C), e7 = ex2f_(sc[2 * t4 + 1][3] * C);
            l0 += (e0 + e1) + (e4 + e5);
            l1 += (e2 + e3) + (e6 + e7);
            splitpack(e0, e1, ph[t4][0], pl[t4][0]);
            splitpack(e2, e3, ph[t4][1], pl[t4][1]);
            splitpack(e4, e5, ph[t4][2], pl[t4][2]);
            splitpack(e6, e7, ph[t4][3], pl[t4][3]);
        }

        // ---- GEMM2: O += P x V (V == K tile, .trans; 3 split terms) ----
#pragma unroll
        for (int t4 = 0; t4 < 4; t4++) {
            int row = 16 * t4 + (lane & 7) + (lane & 8);
#pragma unroll
            for (int jp = 0; jp < 4; jp++) {
                int ch = 2 * jp + (lane >> 4);
                uint32_t vh[4], vl[4];
                LDSM4T(vh, hbb + off(row, ch));
                LDSM4T(vl, lbb + off(row, ch));
                mma_bf16(oacc[2 * jp],     ph[t4], vh + 0);
                mma_bf16(oacc[2 * jp],     ph[t4], vl + 0);
                mma_bf16(oacc[2 * jp],     pl[t4], vh + 0);
                mma_bf16(oacc[2 * jp + 1], ph[t4], vh + 2);
                mma_bf16(oacc[2 * jp + 1], ph[t4], vl + 2);
                mma_bf16(oacc[2 * jp + 1], pl[t4], vh + 2);
            }
        }
        BARG(barid);   // buffer t%3 free for prefetch of t+3
    }

    // ---- normalize + store ----
    l0 += __shfl_xor_sync(0xffffffffu, l0, 1);
    l0 += __shfl_xor_sync(0xffffffffu, l0, 2);
    l1 += __shfl_xor_sync(0xffffffffu, l1, 1);
    l1 += __shfl_xor_sync(0xffffffffu, l1, 2);
    float inv0 = 1.f / l0, inv1 = 1.f / l1;

    const int r = lane >> 2, cb = (lane & 3) * 2;
    size_t base = ((size_t)b * L + (size_t)blockIdx.x * QT + 16 * wid) * DM + h * 64;
    if (outF) {
#pragma unroll
        for (int j = 0; j < 8; j++) {
            *(float2*)(outF + base + (size_t)r * DM + 8 * j + cb) =
                make_float2(oacc[j][0] * inv0, oacc[j][1] * inv0);
            *(float2*)(outF + base + (size_t)(r + 8) * DM + 8 * j + cb) =
                make_float2(oacc[j][2] * inv1, oacc[j][3] * inv1);
        }
    } else {
#pragma unroll
        for (int j = 0; j < 8; j++) {
            uint32_t h0, lp0, h1, lp1;
            splitpack(oacc[j][0] * inv0, oacc[j][1] * inv0, h0, lp0);
            splitpack(oacc[j][2] * inv1, oacc[j][3] * inv1, h1, lp1);
            *(uint32_t*)(outH + base + (size_t)r * DM + 8 * j + cb) = h0;
            *(uint32_t*)(outL + base + (size_t)r * DM + 8 * j + cb) = lp0;
            *(uint32_t*)(outH + base + (size_t)(r + 8) * DM + 8 * j + cb) = h1;
            *(uint32_t*)(outL + base + (size_t)(r + 8) * DM + 8 * j + cb) = lp1;
        }
    }
}

extern "C" void kernel_launch(void* const* d_in, const int* in_sizes, int n_in,
                              void* d_out, int out_size)
{
    const float* R = (const float*)d_in[0];
    const float* Y = (const float*)d_in[1];
    float* out = (float*)d_out;

    const int B = 2, H = 8;
    const int L = in_sizes[0] / (B * DM);   // 2048
    const int S = in_sizes[1] / (B * DM);   // 2048

    __nv_bfloat16 *Yh, *Yl, *Rh, *Rl, *Th, *Tl;
    cudaGetSymbolAddress((void**)&Yh, gYh);
    cudaGetSymbolAddress((void**)&Yl, gYl);
    cudaGetSymbolAddress((void**)&Rh, gRh);
    cudaGetSymbolAddress((void**)&Rl, gRl);
    cudaGetSymbolAddress((void**)&Th, gTh);
    cudaGetSymbolAddress((void**)&Tl, gTl);

    cudaFuncSetAttribute(hopfield_mma, cudaFuncAttributeMaxDynamicSharedMemorySize,
                         SMEM_TOTAL);

    const int n4 = (int)(NELEM / 4);
    presplit<<<(n4 + 255) / 256, 256>>>((const float4*)Y, (uint2*)Yh, (uint2*)Yl, n4);
    presplit<<<(n4 + 255) / 256, 256>>>((const float4*)R, (uint2*)Rh, (uint2*)Rl, n4);

    dim3 grid(L / QT, H, B);
    dim3 block(THREADS);
    // step 1: Q=R -> split tmp
    hopfield_mma<<<grid, block, SMEM_TOTAL>>>(Rh, Rl, Yh, Yl, nullptr, Th, Tl, L, S);
    // step 2: Q=tmp -> fp32 out
    hopfield_mma<<<grid, block, SMEM_TOTAL>>>(Th, Tl, Yh, Yl, out, nullptr, nullptr, L, S);
}

// round 9
// speedup vs baseline: 1.2017x; 1.1076x over previous
#include <cuda_runtime.h>
#include <cuda_bf16.h>
#include <stdint.h>

// Hopfield layer via warp-level bf16 mma.sync (sm_100 target, no tcgen05).
// R9: 8 warps x 32 query rows (QT=256) with the KV tile processed in two
// 32-key halves (GEMM1-half -> softmax-half -> GEMM2-half) to keep register
// pressure under the spill limit. Pre-split bf16 hi/lo inputs, cp.async
// double-buffered KV tiles. 3-term error-corrected bf16 GEMMs, fp32 accum,
// unnormalized softmax (bounded scores), normalize at end.

#define DM 512
#define QT 256     // query rows per CTA (8 warps x 32 rows)
#define ST 64      // kv rows per tile
#define THREADS 256

// dynamic smem layout (bytes): 2 KV buffers (hi 8K + lo 8K each) + Q (hi 32K + lo 32K)
#define KBUF(i)  ((uint32_t)(i) * 16384u)
#define QH0 32768
#define QL0 65536
#define SMEM_TOTAL 98304

#define NELEM (2u * 2048u * 512u)
__device__ __nv_bfloat16 gYh[NELEM], gYl[NELEM];
__device__ __nv_bfloat16 gRh[NELEM], gRl[NELEM];
__device__ __nv_bfloat16 gTh[NELEM], gTl[NELEM];

static __device__ __forceinline__ uint32_t s2u(const void* p) {
    uint32_t a;
    asm("{ .reg .u64 t; cvta.to.shared.u64 t, %1; cvt.u32.u64 %0, t; }"
        : "=r"(a) : "l"(p));
    return a;
}
static __device__ __forceinline__ uint32_t off(int row, int chunk) {
    return (uint32_t)(row * 128 + ((chunk ^ (row & 7)) << 4));
}
static __device__ __forceinline__ float ex2f_(float x) {
    float r; asm("ex2.approx.ftz.f32 %0, %1;" : "=f"(r) : "f"(x)); return r;
}
static __device__ __forceinline__ void splitpack(float x, float y,
                                                 uint32_t& hi, uint32_t& lo) {
    __nv_bfloat16 hx = __float2bfloat16_rn(x), hy = __float2bfloat16_rn(y);
    float rx = x - __bfloat162float(hx), ry = y - __bfloat162float(hy);
    __nv_bfloat16 lx = __float2bfloat16_rn(rx), ly = __float2bfloat16_rn(ry);
    hi = ((uint32_t)__bfloat16_as_ushort(hy) << 16) | (uint32_t)__bfloat16_as_ushort(hx);
    lo = ((uint32_t)__bfloat16_as_ushort(ly) << 16) | (uint32_t)__bfloat16_as_ushort(lx);
}

static __device__ __forceinline__ void mma_bf16(float c[4], const uint32_t a[4],
                                                const uint32_t b[2]) {
    asm volatile(
        "mma.sync.aligned.m16n8k16.row.col.f32.bf16.bf16.f32 "
        "{%0,%1,%2,%3}, {%4,%5,%6,%7}, {%8,%9}, {%0,%1,%2,%3};"
        : "+f"(c[0]), "+f"(c[1]), "+f"(c[2]), "+f"(c[3])
        : "r"(a[0]), "r"(a[1]), "r"(a[2]), "r"(a[3]), "r"(b[0]), "r"(b[1]));
}
#define LDSM4(r, a) \
    asm volatile("ldmatrix.sync.aligned.m8n8.x4.shared.b16 {%0,%1,%2,%3}, [%4];" \
        : "=r"((r)[0]), "=r"((r)[1]), "=r"((r)[2]), "=r"((r)[3]) : "r"(a))
#define LDSM4T(r, a) \
    asm volatile("ldmatrix.sync.aligned.m8n8.x4.trans.shared.b16 {%0,%1,%2,%3}, [%4];" \
        : "=r"((r)[0]), "=r"((r)[1]), "=r"((r)[2]), "=r"((r)[3]) : "r"(a))
#define CPA(dst, src) \
    asm volatile("cp.async.cg.shared.global [%0], [%1], 16;" :: "r"(dst), "l"(src))
#define CPC() asm volatile("cp.async.commit_group;" ::: "memory")
#define CPW(n) asm volatile("cp.async.wait_group %0;" :: "n"(n) : "memory")

__global__ void presplit(const float4* __restrict__ src, uint2* __restrict__ hi,
                         uint2* __restrict__ lo, int n4)
{
    int i = blockIdx.x * blockDim.x + threadIdx.x;
    if (i < n4) {
        float4 x = src[i];
        uint32_t h0, l0, h1, l1;
        splitpack(x.x, x.y, h0, l0);
        splitpack(x.z, x.w, h1, l1);
        hi[i] = make_uint2(h0, h1);
        lo[i] = make_uint2(l0, l1);
    }
}

__global__ __launch_bounds__(THREADS, 1)
void hopfield_mma(const __nv_bfloat16* __restrict__ Qh, const __nv_bfloat16* __restrict__ Ql,
                  const __nv_bfloat16* __restrict__ Kh, const __nv_bfloat16* __restrict__ Kl,
                  float* __restrict__ outF,
                  __nv_bfloat16* __restrict__ outH, __nv_bfloat16* __restrict__ outL,
                  int L, int S)
{
    extern __shared__ __align__(16) uint8_t smem[];
    const uint32_t sb = s2u(smem);
    const uint32_t qhB = sb + QH0, qlB = sb + QL0;

    const int tid = threadIdx.x;
    const int wid = tid >> 5;
    const int lane = tid & 31;
    const int h = blockIdx.y, b = blockIdx.z;
    const float C = 0.125f * 1.4426950408889634f;

    // ---- stage full Q tile (256 rows, hi+lo) ----
    const __nv_bfloat16* qg = Qh + ((size_t)b * L + (size_t)blockIdx.x * QT) * DM + h * 64;
    const __nv_bfloat16* qgl = Ql + ((size_t)b * L + (size_t)blockIdx.x * QT) * DM + h * 64;
    {
        int c = tid & 7, r0 = tid >> 3;   // 0..31
#pragma unroll
        for (int i = 0; i < 8; i++) {
            int row = r0 + i * 32;        // 0..255
            CPA(qhB + off(row, c), (const char*)(qg + (size_t)row * DM) + c * 16);
            CPA(qlB + off(row, c), (const char*)(qgl + (size_t)row * DM) + c * 16);
        }
        CPC(); CPW(0);
    }
    __syncthreads();

    // per-warp A fragments: 2 row-tiles of 16x64 (hi/lo); warp w owns rows 32w..32w+31
    uint32_t qfh[2][4][4], qfl[2][4][4];
#pragma unroll
    for (int rt = 0; rt < 2; rt++) {
        int gr = 32 * wid + 16 * rt + (lane & 15);
#pragma unroll
        for (int t = 0; t < 4; t++) {
            int ch = 2 * t + (lane >> 4);
            LDSM4(qfh[rt][t], qhB + off(gr, ch));
            LDSM4(qfl[rt][t], qlB + off(gr, ch));
        }
    }

    float oacc[2][8][4];
#pragma unroll
    for (int rt = 0; rt < 2; rt++)
#pragma unroll
        for (int j = 0; j < 8; j++)
#pragma unroll
            for (int i = 0; i < 4; i++) oacc[rt][j][i] = 0.f;
    float lsum[2][2] = {{0.f, 0.f}, {0.f, 0.f}};

    const __nv_bfloat16* kg = Kh + (size_t)b * S * DM + h * 64;
    const __nv_bfloat16* kgl = Kl + (size_t)b * S * DM + h * 64;
    const int NT = S / ST;   // 32

    // prefetch tiles 0, 1 into KV buffers
    {
        int c = tid & 7, r0 = tid >> 3;
#pragma unroll
        for (int pf = 0; pf < 2; pf++) {
            uint32_t bh = sb + KBUF(pf), bl = bh + 8192;
            const char* hs = (const char*)(kg + (size_t)pf * ST * DM);
            const char* ls = (const char*)(kgl + (size_t)pf * ST * DM);
#pragma unroll
            for (int i = 0; i < 2; i++) {
                int row = r0 + i * 32;
                CPA(bh + off(row, c), hs + (size_t)row * DM * 2 + c * 16);
                CPA(bl + off(row, c), ls + (size_t)row * DM * 2 + c * 16);
            }
            CPC();
        }
    }

    for (int t = 0; t < NT; t++) {
        CPW(1);
        __syncthreads();
        const uint32_t hbb = sb + KBUF(t & 1);
        const uint32_t lbb = hbb + 8192;

        // ---- process tile in two 32-key halves to bound live registers ----
#pragma unroll
        for (int half = 0; half < 2; half++) {
            // GEMM1-half: sc[rt][4 n-blocks][4]
            float sc[2][4][4];
#pragma unroll
            for (int rt = 0; rt < 2; rt++)
#pragma unroll
                for (int j = 0; j < 4; j++)
#pragma unroll
                    for (int i = 0; i < 4; i++) sc[rt][j][i] = 0.f;

#pragma unroll
            for (int j = 0; j < 4; j++) {
                int row = 32 * half + 8 * j + (lane & 7);
                uint32_t bh[8], bl[8];
                LDSM4(bh + 0, hbb + off(row, (lane >> 3)));
                LDSM4(bh + 4, hbb + off(row, 4 + (lane >> 3)));
                LDSM4(bl + 0, lbb + off(row, (lane >> 3)));
                LDSM4(bl + 4, lbb + off(row, 4 + (lane >> 3)));
#pragma unroll
                for (int t4 = 0; t4 < 4; t4++) {
#pragma unroll
                    for (int rt = 0; rt < 2; rt++) {
                        mma_bf16(sc[rt][j], qfh[rt][t4], bh + 2 * t4);
                        mma_bf16(sc[rt][j], qfh[rt][t4], bl + 2 * t4);
                        mma_bf16(sc[rt][j], qfl[rt][t4], bh + 2 * t4);
                    }
                }
            }

            // softmax-half (unnormalized), pack P (k=32: 2 k-tiles)
            uint32_t ph[2][2][4], pl[2][2][4];
#pragma unroll
            for (int rt = 0; rt < 2; rt++) {
#pragma unroll
                for (int kt = 0; kt < 2; kt++) {
                    float e0 = ex2f_(sc[rt][2 * kt][0] * C),     e1 = ex2f_(sc[rt][2 * kt][1] * C);
                    float e2 = ex2f_(sc[rt][2 * kt][2] * C),     e3 = ex2f_(sc[rt][2 * kt][3] * C);
                    float e4 = ex2f_(sc[rt][2 * kt + 1][0] * C), e5 = ex2f_(sc[rt][2 * kt + 1][1] * C);
                    float e6 = ex2f_(sc[rt][2 * kt + 1][2] * C), e7 = ex2f_(sc[rt][2 * kt + 1][3] * C);
                    lsum[rt][0] += (e0 + e1) + (e4 + e5);
                    lsum[rt][1] += (e2 + e3) + (e6 + e7);
                    splitpack(e0, e1, ph[rt][kt][0], pl[rt][kt][0]);
                    splitpack(e2, e3, ph[rt][kt][1], pl[rt][kt][1]);
                    splitpack(e4, e5, ph[rt][kt][2], pl[rt][kt][2]);
                    splitpack(e6, e7, ph[rt][kt][3], pl[rt][kt][3]);
                }
            }

            // GEMM2-half: O += P(:,32half..32half+31) x V(rows 32half..)
#pragma unroll
            for (int kt = 0; kt < 2; kt++) {
                int row = 32 * half + 16 * kt + (lane & 7) + (lane & 8);
#pragma unroll
                for (int jp = 0; jp < 4; jp++) {
                    int ch = 2 * jp + (lane >> 4);
                    uint32_t vh[4], vl[4];
                    LDSM4T(vh, hbb + off(row, ch));
                    LDSM4T(vl, lbb + off(row, ch));
#pragma unroll
                    for (int rt = 0; rt < 2; rt++) {
                        mma_bf16(oacc[rt][2 * jp],     ph[rt][kt], vh + 0);
                        mma_bf16(oacc[rt][2 * jp],     ph[rt][kt], vl + 0);
                        mma_bf16(oacc[rt][2 * jp],     pl[rt][kt], vh + 0);
                        mma_bf16(oacc[rt][2 * jp + 1], ph[rt][kt], vh + 2);
                        mma_bf16(oacc[rt][2 * jp + 1], ph[rt][kt], vl + 2);
                        mma_bf16(oacc[rt][2 * jp + 1], pl[rt][kt], vh + 2);
                    }
                }
            }
        }
        __syncthreads();

        // prefetch tile t+2 into the buffer just freed
        if (t + 2 < NT) {
            int c = tid & 7, r0 = tid >> 3;
            const char* hs = (const char*)(kg + (size_t)(t + 2) * ST * DM);
            const char* ls = (const char*)(kgl + (size_t)(t + 2) * ST * DM);
#pragma unroll
            for (int i = 0; i < 2; i++) {
                int row = r0 + i * 32;
                CPA(hbb + off(row, c), hs + (size_t)row * DM * 2 + c * 16);
                CPA(lbb + off(row, c), ls + (size_t)row * DM * 2 + c * 16);
            }
        }
        CPC();
    }

    // ---- normalize + store ----
    const int r = lane >> 2, cb = (lane & 3) * 2;
#pragma unroll
    for (int rt = 0; rt < 2; rt++) {
        float l0 = lsum[rt][0], l1 = lsum[rt][1];
        l0 += __shfl_xor_sync(0xffffffffu, l0, 1);
        l0 += __shfl_xor_sync(0xffffffffu, l0, 2);
        l1 += __shfl_xor_sync(0xffffffffu, l1, 1);
        l1 += __shfl_xor_sync(0xffffffffu, l1, 2);
        float inv0 = 1.f / l0, inv1 = 1.f / l1;

        size_t base = ((size_t)b * L + (size_t)blockIdx.x * QT + 32 * wid + 16 * rt) * DM
                    + h * 64;
        if (outF) {
#pragma unroll
            for (int j = 0; j < 8; j++) {
                *(float2*)(outF + base + (size_t)r * DM + 8 * j + cb) =
                    make_float2(oacc[rt][j][0] * inv0, oacc[rt][j][1] * inv0);
                *(float2*)(outF + base + (size_t)(r + 8) * DM + 8 * j + cb) =
                    make_float2(oacc[rt][j][2] * inv1, oacc[rt][j][3] * inv1);
            }
        } else {
#pragma unroll
            for (int j = 0; j < 8; j++) {
                uint32_t h0, lp0, h1, lp1;
                splitpack(oacc[rt][j][0] * inv0, oacc[rt][j][1] * inv0, h0, lp0);
                splitpack(oacc[rt][j][2] * inv1, oacc[rt][j][3] * inv1, h1, lp1);
                *(uint32_t*)(outH + base + (size_t)r * DM + 8 * j + cb) = h0;
                *(uint32_t*)(outL + base + (size_t)r * DM + 8 * j + cb) = lp0;
                *(uint32_t*)(outH + base + (size_t)(r + 8) * DM + 8 * j + cb) = h1;
                *(uint32_t*)(outL + base + (size_t)(r + 8) * DM + 8 * j + cb) = lp1;
            }
        }
    }
}

extern "C" void kernel_launch(void* const* d_in, const int* in_sizes, int n_in,
                              void* d_out, int out_size)
{
    const float* R = (const float*)d_in[0];
    const float* Y = (const float*)d_in[1];
    float* out = (float*)d_out;

    const int B = 2, H = 8;
    const int L = in_sizes[0] / (B * DM);   // 2048
    const int S = in_sizes[1] / (B * DM);   // 2048

    __nv_bfloat16 *Yh, *Yl, *Rh, *Rl, *Th, *Tl;
    cudaGetSymbolAddress((void**)&Yh, gYh);
    cudaGetSymbolAddress((void**)&Yl, gYl);
    cudaGetSymbolAddress((void**)&Rh, gRh);
    cudaGetSymbolAddress((void**)&Rl, gRl);
    cudaGetSymbolAddress((void**)&Th, gTh);
    cudaGetSymbolAddress((void**)&Tl, gTl);

    cudaFuncSetAttribute(hopfield_mma, cudaFuncAttributeMaxDynamicSharedMemorySize,
                         SMEM_TOTAL);

    const int n4 = (int)(NELEM / 4);
    presplit<<<(n4 + 255) / 256, 256>>>((const float4*)Y, (uint2*)Yh, (uint2*)Yl, n4);
    presplit<<<(n4 + 255) / 256, 256>>>((const float4*)R, (uint2*)Rh, (uint2*)Rl, n4);

    dim3 grid(L / QT, H, B);
    dim3 block(THREADS);
    // step 1: Q=R -> split tmp
    hopfield_mma<<<grid, block, SMEM_TOTAL>>>(Rh, Rl, Yh, Yl, nullptr, Th, Tl, L, S);
    // step 2: Q=tmp -> fp32 out
    hopfield_mma<<<grid, block, SMEM_TOTAL>>>(Th, Tl, Yh, Yl, out, nullptr, nullptr, L, S);
}

// round 10
// speedup vs baseline: 3.0096x; 2.5045x over previous
#include <cuda_runtime.h>
#include <cuda_fp16.h>
#include <stdint.h>

// Hopfield layer via warp-level fp16 mma.sync (sm_100 target, no tcgen05).
// R10: pure fp16 operands + fp32 accumulators (single-term GEMMs; fp16's
// 2^-12 rounding keeps rel_err ~3e-4 < 1e-3). 8 warps x 32 query rows
// (QT=256), KV tile processed in two 32-key halves, cp.async double-buffered
// KV, unnormalized softmax (bounded scores), normalize at end.

#define DM 512
#define QT 256
#define ST 64
#define THREADS 256

// dynamic smem: 2 KV buffers (8KB each) + Q tile (32KB)
#define KBUF(i)  ((uint32_t)(i) * 8192u)
#define QB0 16384
#define SMEM_TOTAL 49152

#define NELEM (2u * 2048u * 512u)
__device__ __half gYh[NELEM];
__device__ __half gRh[NELEM];
__device__ __half gTh[NELEM];

static __device__ __forceinline__ uint32_t s2u(const void* p) {
    uint32_t a;
    asm("{ .reg .u64 t; cvta.to.shared.u64 t, %1; cvt.u32.u64 %0, t; }"
        : "=r"(a) : "l"(p));
    return a;
}
static __device__ __forceinline__ uint32_t off(int row, int chunk) {
    return (uint32_t)(row * 128 + ((chunk ^ (row & 7)) << 4));
}
static __device__ __forceinline__ float ex2f_(float x) {
    float r; asm("ex2.approx.ftz.f32 %0, %1;" : "=f"(r) : "f"(x)); return r;
}
static __device__ __forceinline__ uint32_t packh(float x, float y) {
    __half hx = __float2half_rn(x), hy = __float2half_rn(y);
    return ((uint32_t)__half_as_ushort(hy) << 16) | (uint32_t)__half_as_ushort(hx);
}

static __device__ __forceinline__ void mma_f16(float c[4], const uint32_t a[4],
                                               const uint32_t b[2]) {
    asm volatile(
        "mma.sync.aligned.m16n8k16.row.col.f32.f16.f16.f32 "
        "{%0,%1,%2,%3}, {%4,%5,%6,%7}, {%8,%9}, {%0,%1,%2,%3};"
        : "+f"(c[0]), "+f"(c[1]), "+f"(c[2]), "+f"(c[3])
        : "r"(a[0]), "r"(a[1]), "r"(a[2]), "r"(a[3]), "r"(b[0]), "r"(b[1]));
}
#define LDSM4(r, a) \
    asm volatile("ldmatrix.sync.aligned.m8n8.x4.shared.b16 {%0,%1,%2,%3}, [%4];" \
        : "=r"((r)[0]), "=r"((r)[1]), "=r"((r)[2]), "=r"((r)[3]) : "r"(a))
#define LDSM4T(r, a) \
    asm volatile("ldmatrix.sync.aligned.m8n8.x4.trans.shared.b16 {%0,%1,%2,%3}, [%4];" \
        : "=r"((r)[0]), "=r"((r)[1]), "=r"((r)[2]), "=r"((r)[3]) : "r"(a))
#define CPA(dst, src) \
    asm volatile("cp.async.cg.shared.global [%0], [%1], 16;" :: "r"(dst), "l"(src))
#define CPC() asm volatile("cp.async.commit_group;" ::: "memory")
#define CPW(n) asm volatile("cp.async.wait_group %0;" :: "n"(n) : "memory")

// fp32 -> fp16 convert (packed pairs)
__global__ void tohalf(const float4* __restrict__ src, uint2* __restrict__ dst, int n4)
{
    int i = blockIdx.x * blockDim.x + threadIdx.x;
    if (i < n4) {
        float4 x = src[i];
        dst[i] = make_uint2(packh(x.x, x.y), packh(x.z, x.w));
    }
}

__global__ __launch_bounds__(THREADS, 1)
void hopfield_mma(const __half* __restrict__ Qm, const __half* __restrict__ Km,
                  float* __restrict__ outF, __half* __restrict__ outH,
                  int L, int S)
{
    extern __shared__ __align__(16) uint8_t smem[];
    const uint32_t sb = s2u(smem);
    const uint32_t qB = sb + QB0;

    const int tid = threadIdx.x;
    const int wid = tid >> 5;
    const int lane = tid & 31;
    const int h = blockIdx.y, b = blockIdx.z;
    const float C = 0.125f * 1.4426950408889634f;

    // ---- stage full Q tile (256 rows x 64 halves = 32KB) ----
    const __half* qg = Qm + ((size_t)b * L + (size_t)blockIdx.x * QT) * DM + h * 64;
    {
        int c = tid & 7, r0 = tid >> 3;   // 0..31
#pragma unroll
        for (int i = 0; i < 8; i++) {
            int row = r0 + i * 32;        // 0..255
            CPA(qB + off(row, c), (const char*)(qg + (size_t)row * DM) + c * 16);
        }
        CPC(); CPW(0);
    }
    __syncthreads();

    // per-warp A fragments: 2 row-tiles of 16x64; warp w owns rows 32w..32w+31
    uint32_t qf[2][4][4];
#pragma unroll
    for (int rt = 0; rt < 2; rt++) {
        int gr = 32 * wid + 16 * rt + (lane & 15);
#pragma unroll
        for (int t = 0; t < 4; t++) {
            int ch = 2 * t + (lane >> 4);
            LDSM4(qf[rt][t], qB + off(gr, ch));
        }
    }

    float oacc[2][8][4];
#pragma unroll
    for (int rt = 0; rt < 2; rt++)
#pragma unroll
        for (int j = 0; j < 8; j++)
#pragma unroll
            for (int i = 0; i < 4; i++) oacc[rt][j][i] = 0.f;
    float lsum[2][2] = {{0.f, 0.f}, {0.f, 0.f}};

    const __half* kg = Km + (size_t)b * S * DM + h * 64;
    const int NT = S / ST;   // 32

    // prefetch tiles 0, 1
    {
        int c = tid & 7, r0 = tid >> 3;
#pragma unroll
        for (int pf = 0; pf < 2; pf++) {
            uint32_t bh = sb + KBUF(pf);
            const char* hs = (const char*)(kg + (size_t)pf * ST * DM);
#pragma unroll
            for (int i = 0; i < 2; i++) {
                int row = r0 + i * 32;
                CPA(bh + off(row, c), hs + (size_t)row * DM * 2 + c * 16);
            }
            CPC();
        }
    }

    for (int t = 0; t < NT; t++) {
        CPW(1);
        __syncthreads();
        const uint32_t kb = sb + KBUF(t & 1);

        // ---- process tile in two 32-key halves (bounds live registers) ----
#pragma unroll
        for (int half = 0; half < 2; half++) {
            // GEMM1-half: sc[rt][4 n-blocks][4] = Q x K^T
            float sc[2][4][4];
#pragma unroll
            for (int rt = 0; rt < 2; rt++)
#pragma unroll
                for (int j = 0; j < 4; j++)
#pragma unroll
                    for (int i = 0; i < 4; i++) sc[rt][j][i] = 0.f;

#pragma unroll
            for (int j = 0; j < 4; j++) {
                int row = 32 * half + 8 * j + (lane & 7);
                uint32_t bh[8];
                LDSM4(bh + 0, kb + off(row, (lane >> 3)));
                LDSM4(bh + 4, kb + off(row, 4 + (lane >> 3)));
#pragma unroll
                for (int t4 = 0; t4 < 4; t4++)
#pragma unroll
                    for (int rt = 0; rt < 2; rt++)
                        mma_f16(sc[rt][j], qf[rt][t4], bh + 2 * t4);
            }

            // softmax-half (unnormalized), pack P to fp16 A-fragments
            uint32_t ph[2][2][4];
#pragma unroll
            for (int rt = 0; rt < 2; rt++) {
#pragma unroll
                for (int kt = 0; kt < 2; kt++) {
                    float e0 = ex2f_(sc[rt][2 * kt][0] * C),     e1 = ex2f_(sc[rt][2 * kt][1] * C);
                    float e2 = ex2f_(sc[rt][2 * kt][2] * C),     e3 = ex2f_(sc[rt][2 * kt][3] * C);
                    float e4 = ex2f_(sc[rt][2 * kt + 1][0] * C), e5 = ex2f_(sc[rt][2 * kt + 1][1] * C);
                    float e6 = ex2f_(sc[rt][2 * kt + 1][2] * C), e7 = ex2f_(sc[rt][2 * kt + 1][3] * C);
                    lsum[rt][0] += (e0 + e1) + (e4 + e5);
                    lsum[rt][1] += (e2 + e3) + (e6 + e7);
                    ph[rt][kt][0] = packh(e0, e1);
                    ph[rt][kt][1] = packh(e2, e3);
                    ph[rt][kt][2] = packh(e4, e5);
                    ph[rt][kt][3] = packh(e6, e7);
                }
            }

            // GEMM2-half: O += P x V (V == K tile, .trans)
#pragma unroll
            for (int kt = 0; kt < 2; kt++) {
                int row = 32 * half + 16 * kt + (lane & 7) + (lane & 8);
#pragma unroll
                for (int jp = 0; jp < 4; jp++) {
                    int ch = 2 * jp + (lane >> 4);
                    uint32_t vh[4];
                    LDSM4T(vh, kb + off(row, ch));
#pragma unroll
                    for (int rt = 0; rt < 2; rt++) {
                        mma_f16(oacc[rt][2 * jp],     ph[rt][kt], vh + 0);
                        mma_f16(oacc[rt][2 * jp + 1], ph[rt][kt], vh + 2);
                    }
                }
            }
        }
        __syncthreads();

        // prefetch tile t+2 into the buffer just freed
        if (t + 2 < NT) {
            int c = tid & 7, r0 = tid >> 3;
            const char* hs = (const char*)(kg + (size_t)(t + 2) * ST * DM);
#pragma unroll
            for (int i = 0; i < 2; i++) {
                int row = r0 + i * 32;
                CPA(kb + off(row, c), hs + (size_t)row * DM * 2 + c * 16);
            }
        }
        CPC();
    }

    // ---- normalize + store ----
    const int r = lane >> 2, cb = (lane & 3) * 2;
#pragma unroll
    for (int rt = 0; rt < 2; rt++) {
        float l0 = lsum[rt][0], l1 = lsum[rt][1];
        l0 += __shfl_xor_sync(0xffffffffu, l0, 1);
        l0 += __shfl_xor_sync(0xffffffffu, l0, 2);
        l1 += __shfl_xor_sync(0xffffffffu, l1, 1);
        l1 += __shfl_xor_sync(0xffffffffu, l1, 2);
        float inv0 = 1.f / l0, inv1 = 1.f / l1;

        size_t base = ((size_t)b * L + (size_t)blockIdx.x * QT + 32 * wid + 16 * rt) * DM
                    + h * 64;
        if (outF) {
#pragma unroll
            for (int j = 0; j < 8; j++) {
                *(float2*)(outF + base + (size_t)r * DM + 8 * j + cb) =
                    make_float2(oacc[rt][j][0] * inv0, oacc[rt][j][1] * inv0);
                *(float2*)(outF + base + (size_t)(r + 8) * DM + 8 * j + cb) =
                    make_float2(oacc[rt][j][2] * inv1, oacc[rt][j][3] * inv1);
            }
        } else {
#pragma unroll
            for (int j = 0; j < 8; j++) {
                *(uint32_t*)(outH + base + (size_t)r * DM + 8 * j + cb) =
                    packh(oacc[rt][j][0] * inv0, oacc[rt][j][1] * inv0);
                *(uint32_t*)(outH + base + (size_t)(r + 8) * DM + 8 * j + cb) =
                    packh(oacc[rt][j][2] * inv1, oacc[rt][j][3] * inv1);
            }
        }
    }
}

extern "C" void kernel_launch(void* const* d_in, const int* in_sizes, int n_in,
                              void* d_out, int out_size)
{
    const float* R = (const float*)d_in[0];
    const float* Y = (const float*)d_in[1];
    float* out = (float*)d_out;

    const int B = 2, H = 8;
    const int L = in_sizes[0] / (B * DM);   // 2048
    const int S = in_sizes[1] / (B * DM);   // 2048

    __half *Yh, *Rh, *Th;
    cudaGetSymbolAddress((void**)&Yh, gYh);
    cudaGetSymbolAddress((void**)&Rh, gRh);
    cudaGetSymbolAddress((void**)&Th, gTh);

    cudaFuncSetAttribute(hopfield_mma, cudaFuncAttributeMaxDynamicSharedMemorySize,
                         SMEM_TOTAL);

    const int n4 = (int)(NELEM / 4);
    tohalf<<<(n4 + 255) / 256, 256>>>((const float4*)Y, (uint2*)Yh, n4);
    tohalf<<<(n4 + 255) / 256, 256>>>((const float4*)R, (uint2*)Rh, n4);

    dim3 grid(L / QT, H, B);
    dim3 block(THREADS);
    // step 1: Q=R -> fp16 tmp
    hopfield_mma<<<grid, block, SMEM_TOTAL>>>(Rh, Yh, nullptr, Th, L, S);
    // step 2: Q=tmp -> fp32 out
    hopfield_mma<<<grid, block, SMEM_TOTAL>>>(Th, Yh, out, nullptr, L, S);
}